// round 7
// baseline (speedup 1.0000x reference)
#include <cuda_runtime.h>
#include <cstdint>

// Problem constants
#define Bq      64
#define SMAX    2048
#define PAGEq   128
#define Hq      32
#define KVHq    8
#define Gq      4
#define HDq     128
#define SCALEq  0.08838834764831845f   // 128^-0.5

#define CHUNK   128        // tokens per CTA split (one KV page)
#define NSPLIT  16         // SMAX / CHUNK
#define WTOK    32         // tokens per warp
#define BDIM    128

#define KVSTRIDE  (KVHq*HDq)                 // floats between tokens
#define BLKSTRIDE ((long)PAGEq*KVHq*HDq)     // floats per KV block

// split partials + completion counters
__device__ float P_acc[Bq*KVHq*NSPLIT*Gq*HDq];
__device__ float P_m[Bq*KVHq*NSPLIT*Gq];
__device__ float P_l[Bq*KVHq*NSPLIT*Gq];
__device__ int   P_cnt[Bq*KVHq];             // zero-init; reset by combiner each launch

__device__ __forceinline__ float ldcg(const float* p) {
    float v; asm volatile("ld.global.cg.f32 %0, [%1];" : "=f"(v) : "l"(p)); return v;
}
__device__ __forceinline__ void cp16(uint32_t s, const void* g) {
    asm volatile("cp.async.cg.shared.global [%0], [%1], 16;\n" :: "r"(s), "l"(g));
}
__device__ __forceinline__ void cp_commit() { asm volatile("cp.async.commit_group;\n"); }
__device__ __forceinline__ void cp_wait1()  { asm volatile("cp.async.wait_group 1;\n"); }

// butterfly stage on 16 live values
#define BFLY_STAGE(D)                                              \
    _Pragma("unroll")                                              \
    for (int j = 0; j < (D); j++) {                                \
        bool  hi   = (lane & (D)) != 0;                            \
        float send = hi ? r[j] : r[j + (D)];                       \
        float recv = __shfl_xor_sync(0xffffffffu, send, (D));      \
        float keep = hi ? r[j + (D)] : r[j];                       \
        r[j] = keep + recv;                                        \
    }

__global__ __launch_bounds__(BDIM, 4) void attn_split_kernel(
    const int* __restrict__ req_to_token,
    const int* __restrict__ req_pool,
    const int* __restrict__ seq_lens,
    const float* __restrict__ query,
    const float* __restrict__ k_cache,
    const float* __restrict__ v_cache,
    float* __restrict__ outp)
{
    // per-warp V staging (double buffer); overlaid by warp-combine buffers after the loop
    __shared__ float smbuf[4][2][8 * HDq];   // 32 KB
    __shared__ int   s_last;

    const int split = blockIdx.x;
    const int kvh   = blockIdx.y;
    const int b     = blockIdx.z;

    const int L  = seq_lens[b];
    const int c0 = split * CHUNK;
    if (c0 >= L) return;
    const int ns = (L + CHUNK - 1) / CHUNK;

    const int w    = threadIdx.x >> 5;
    const int lane = threadIdx.x & 31;
    const int tid  = threadIdx.x;

    // ---- Q in registers, pre-scaled. lane owns d = 4*lane..4*lane+3 ----
    float4 q[4];
    {
        const float* Qb = query + ((long)b * Hq + kvh * Gq) * HDq + 4 * lane;
        #pragma unroll
        for (int h = 0; h < 4; h++) {
            float4 t = *(const float4*)(Qb + h * HDq);
            q[h] = make_float4(t.x * SCALEq, t.y * SCALEq, t.z * SCALEq, t.w * SCALEq);
        }
    }

    // ---- warp token range: CTA owns one page; warp owns 32 tokens of it ----
    const int warpStart = c0 + w * WTOK;
    const int req  = req_pool[b];
    const long blk = (long)(req_to_token[req * SMAX + (c0 >> 7) * PAGEq] >> 7);
    const long off = blk * BLKSTRIDE + (long)(warpStart & 127) * KVSTRIDE + kvh * HDq + 4 * lane;
    const float* kp = k_cache + off;
    const float* vp = v_cache + off;

    int nt = L - warpStart;
    if (nt < 0) nt = 0;
    if (nt > WTOK) nt = WTOK;
    const int n_it = (nt + 7) >> 3;          // <= 4

    // this lane's V smem slices
    const uint32_t vs0 = (uint32_t)__cvta_generic_to_shared(&smbuf[w][0][4 * lane]);
    const uint32_t vs1 = (uint32_t)__cvta_generic_to_shared(&smbuf[w][1][4 * lane]);
    auto stageV = [&](int buf, int it) {
        const float* vq = vp + (long)(it * 8) * KVSTRIDE;
        uint32_t d = buf ? vs1 : vs0;
        #pragma unroll
        for (int t = 0; t < 8; t++)
            cp16(d + (uint32_t)(t * HDq) * 4, vq + (long)t * KVSTRIDE);
    };

    float4 out[4];
    #pragma unroll
    for (int h = 0; h < 4; h++) out[h] = make_float4(0.f, 0.f, 0.f, 0.f);
    float m_run = -1e30f, l_run = 0.f;   // state for head h = lane&3

    float4 kcur[8];
    if (n_it > 0) {
        #pragma unroll
        for (int t = 0; t < 8; t++) kcur[t] = __ldcs((const float4*)(kp + (long)t * KVSTRIDE));
        stageV(0, 0); cp_commit();
    }

    #pragma unroll 4
    for (int it = 0; it < n_it; it++) {
        // ---- prefetch next group: K into registers, V into smem ----
        float4 knext[8];
        if (it + 1 < n_it) {
            const float* kq = kp + (long)((it + 1) * 8) * KVSTRIDE;
            #pragma unroll
            for (int t = 0; t < 8; t++) knext[t] = __ldcs((const float4*)(kq + t * KVSTRIDE));
            stageV((it + 1) & 1, it + 1);
        }
        cp_commit();

        // ---- dot with fused stage-16 exchange: pairs (t, t+4) ----
        float r[16];
        #pragma unroll
        for (int t = 0; t < 4; t++) {
            #pragma unroll
            for (int h = 0; h < 4; h++) {
                float a = kcur[t].x * q[h].x;
                a = fmaf(kcur[t].y, q[h].y, a);
                a = fmaf(kcur[t].z, q[h].z, a);
                a = fmaf(kcur[t].w, q[h].w, a);
                float bb = kcur[t + 4].x * q[h].x;
                bb = fmaf(kcur[t + 4].y, q[h].y, bb);
                bb = fmaf(kcur[t + 4].z, q[h].z, bb);
                bb = fmaf(kcur[t + 4].w, q[h].w, bb);
                bool  hi   = (lane & 16) != 0;
                float send = hi ? a : bb;
                float recv = __shfl_xor_sync(0xffffffffu, send, 16);
                r[t * 4 + h] = (hi ? bb : a) + recv;
            }
        }
        BFLY_STAGE(8) BFLY_STAGE(4) BFLY_STAGE(2) BFLY_STAGE(1)
        float s = r[0];                      // score for (t = lane>>2, h = lane&3)

        const int tok = warpStart + it * 8 + (lane >> 2);
        if (tok >= L) s = -1e30f;

        // per-head max / sum over 8 tokens (lanes stride 4 share a head)
        float mt = s;
        mt = fmaxf(mt, __shfl_xor_sync(0xffffffffu, mt, 4));
        mt = fmaxf(mt, __shfl_xor_sync(0xffffffffu, mt, 8));
        mt = fmaxf(mt, __shfl_xor_sync(0xffffffffu, mt, 16));
        float m_new = fmaxf(m_run, mt);
        float p  = __expf(s - m_new);
        float ps = p;
        ps += __shfl_xor_sync(0xffffffffu, ps, 4);
        ps += __shfl_xor_sync(0xffffffffu, ps, 8);
        ps += __shfl_xor_sync(0xffffffffu, ps, 16);
        float csc = __expf(m_run - m_new);
        l_run = l_run * csc + ps;
        m_run = m_new;

        #pragma unroll
        for (int h = 0; h < 4; h++) {
            float c = __shfl_sync(0xffffffffu, csc, h);
            out[h].x *= c; out[h].y *= c; out[h].z *= c; out[h].w *= c;
        }

        // ---- V group resident; P·V ----
        cp_wait1();
        const float* V = &smbuf[w][it & 1][4 * lane];
        #pragma unroll
        for (int t = 0; t < 8; t++) {
            float4 v4 = *(const float4*)(V + t * HDq);
            #pragma unroll
            for (int h = 0; h < 4; h++) {
                float pp = __shfl_sync(0xffffffffu, p, t * 4 + h);
                out[h].x = fmaf(pp, v4.x, out[h].x);
                out[h].y = fmaf(pp, v4.y, out[h].y);
                out[h].z = fmaf(pp, v4.z, out[h].z);
                out[h].w = fmaf(pp, v4.w, out[h].w);
            }
        }

        // rotate K pipeline
        #pragma unroll
        for (int t = 0; t < 8; t++) kcur[t] = knext[t];
    }

    // ---- CTA-internal combine: overlay warp buffers on this warp's V smem ----
    float* wacc = &smbuf[w][0][0];            // [4][128]
    float* wml  = &smbuf[w][1][0];            // m[4], l at +8
    #pragma unroll
    for (int h = 0; h < 4; h++)
        *(float4*)&wacc[h * HDq + 4 * lane] = out[h];
    if (lane < 4) { wml[lane] = m_run; wml[8 + lane] = l_run; }
    __syncthreads();

    const int  gidx = b * KVHq + kvh;
    const long base = (long)gidx * NSPLIT * Gq + (long)split * Gq;
    #pragma unroll
    for (int h = 0; h < 4; h++) {
        float m0 = smbuf[0][1][h], m1 = smbuf[1][1][h];
        float m2 = smbuf[2][1][h], m3 = smbuf[3][1][h];
        float M = fmaxf(fmaxf(m0, m1), fmaxf(m2, m3));
        float e0 = __expf(m0 - M), e1 = __expf(m1 - M);
        float e2 = __expf(m2 - M), e3 = __expf(m3 - M);
        float acc = e0 * smbuf[0][0][h * HDq + tid] + e1 * smbuf[1][0][h * HDq + tid]
                  + e2 * smbuf[2][0][h * HDq + tid] + e3 * smbuf[3][0][h * HDq + tid];
        P_acc[(base + h) * HDq + tid] = acc;
        if (tid == 0) {
            P_m[base + h] = M;
            P_l[base + h] = e0 * smbuf[0][1][8 + h] + e1 * smbuf[1][1][8 + h]
                          + e2 * smbuf[2][1][8 + h] + e3 * smbuf[3][1][8 + h];
        }
    }

    // ---- last-CTA-done global combine for this (b,kvh) ----
    __threadfence();
    if (tid == 0) {
        int old = atomicAdd(&P_cnt[gidx], 1);
        s_last = (old == ns - 1);
    }
    __syncthreads();
    if (!s_last) return;
    if (tid == 0) P_cnt[gidx] = 0;          // reset for next graph replay

    const long base0 = (long)gidx * NSPLIT * Gq;
    #pragma unroll
    for (int h = 0; h < 4; h++) {
        float ms[NSPLIT], ls[NSPLIT];
        #pragma unroll
        for (int s = 0; s < NSPLIT; s++) {
            bool v = s < ns;
            ms[s] = v ? ldcg(&P_m[base0 + s * Gq + h]) : -1e30f;
            ls[s] = v ? ldcg(&P_l[base0 + s * Gq + h]) : 0.f;
        }
        float M = -1e30f;
        #pragma unroll
        for (int s = 0; s < NSPLIT; s++) M = fmaxf(M, ms[s]);
        float acc = 0.f, l = 0.f;
        #pragma unroll
        for (int s = 0; s < NSPLIT; s++) {
            float e = __expf(ms[s] - M);
            l += e * ls[s];
            float a = (s < ns) ? ldcg(&P_acc[(base0 + s * Gq + h) * HDq + tid]) : 0.f;
            acc += e * a;
        }
        outp[((long)b * Hq + kvh * Gq + h) * HDq + tid] = acc / l;
    }
}

extern "C" void kernel_launch(void* const* d_in, const int* in_sizes, int n_in,
                              void* d_out, int out_size)
{
    const int*   req_to_token = (const int*)d_in[0];
    const int*   req_pool     = (const int*)d_in[1];
    const int*   seq_lens     = (const int*)d_in[2];
    const float* query        = (const float*)d_in[3];
    const float* k_cache      = (const float*)d_in[4];
    const float* v_cache      = (const float*)d_in[5];
    float*       out          = (float*)d_out;

    dim3 grid1(NSPLIT, KVHq, Bq);
    attn_split_kernel<<<grid1, BDIM>>>(
        req_to_token, req_pool, seq_lens, query, k_cache, v_cache, out);
}

// round 9
// speedup vs baseline: 1.2041x; 1.2041x over previous
#include <cuda_runtime.h>
#include <cstdint>

// Problem constants
#define Bq      64
#define SMAX    2048
#define PAGEq   128
#define Hq      32
#define KVHq    8
#define Gq      4
#define HDq     128
#define SCALEq  0.08838834764831845f   // 128^-0.5

#define CHUNK   256        // tokens per CTA split
#define NSPLIT  8          // SMAX / CHUNK
#define WTOK    64         // tokens per warp
#define BDIM    128

#define KVSTRIDE  (KVHq*HDq)                 // floats between tokens
#define BLKSTRIDE ((long)PAGEq*KVHq*HDq)     // floats per KV block

// split partials + completion counters
__device__ float P_acc[Bq*KVHq*NSPLIT*Gq*HDq];
__device__ float P_m[Bq*KVHq*NSPLIT*Gq];
__device__ float P_l[Bq*KVHq*NSPLIT*Gq];
__device__ int   P_cnt[Bq*KVHq];             // zero-init; reset by combiner each launch

__device__ __forceinline__ float ldcg(const float* p) {
    float v; asm volatile("ld.global.cg.f32 %0, [%1];" : "=f"(v) : "l"(p)); return v;
}
__device__ __forceinline__ void cp16(uint32_t s, const void* g) {
    asm volatile("cp.async.cg.shared.global [%0], [%1], 16;\n" :: "r"(s), "l"(g));
}
__device__ __forceinline__ void cp_commit() { asm volatile("cp.async.commit_group;\n"); }
__device__ __forceinline__ void cp_wait1()  { asm volatile("cp.async.wait_group 1;\n"); }

// butterfly stage on 16 live values
#define BFLY_STAGE(D)                                              \
    _Pragma("unroll")                                              \
    for (int j = 0; j < (D); j++) {                                \
        bool  hi   = (lane & (D)) != 0;                            \
        float send = hi ? r[j] : r[j + (D)];                       \
        float recv = __shfl_xor_sync(0xffffffffu, send, (D));      \
        float keep = hi ? r[j + (D)] : r[j];                       \
        r[j] = keep + recv;                                        \
    }

__global__ __launch_bounds__(BDIM, 6) void attn_split_kernel(
    const int* __restrict__ req_to_token,
    const int* __restrict__ req_pool,
    const int* __restrict__ seq_lens,
    const float* __restrict__ query,
    const float* __restrict__ k_cache,
    const float* __restrict__ v_cache,
    float* __restrict__ outp)
{
    // per-warp V staging (double buffer); overlaid by warp-combine buffers after the loop
    __shared__ float smbuf[4][2][8 * HDq];   // 32 KB
    __shared__ int   s_last;

    const int split = blockIdx.x;
    const int kvh   = blockIdx.y;
    const int b     = blockIdx.z;

    const int L  = seq_lens[b];
    const int c0 = split * CHUNK;
    if (c0 >= L) return;
    const int ns = (L + CHUNK - 1) / CHUNK;

    const int w    = threadIdx.x >> 5;
    const int lane = threadIdx.x & 31;
    const int tid  = threadIdx.x;

    // ---- Q in registers, pre-scaled. lane owns d = 4*lane..4*lane+3 ----
    float4 q[4];
    {
        const float* Qb = query + ((long)b * Hq + kvh * Gq) * HDq + 4 * lane;
        #pragma unroll
        for (int h = 0; h < 4; h++) {
            float4 t = *(const float4*)(Qb + h * HDq);
            q[h] = make_float4(t.x * SCALEq, t.y * SCALEq, t.z * SCALEq, t.w * SCALEq);
        }
    }

    // ---- warp token range (stays within one KV page) ----
    const int warpStart = c0 + w * WTOK;
    const int req  = req_pool[b];
    const long blk = (long)(req_to_token[req * SMAX + (warpStart >> 7) * PAGEq] >> 7);
    const long off = blk * BLKSTRIDE + (long)(warpStart & 127) * KVSTRIDE + kvh * HDq + 4 * lane;
    const float* kp = k_cache + off;
    const float* vp = v_cache + off;

    int nt = L - warpStart;
    if (nt < 0) nt = 0;
    if (nt > WTOK) nt = WTOK;
    const int n_it = (nt + 7) >> 3;

    // this lane's V smem slices
    const uint32_t vs0 = (uint32_t)__cvta_generic_to_shared(&smbuf[w][0][4 * lane]);
    const uint32_t vs1 = (uint32_t)__cvta_generic_to_shared(&smbuf[w][1][4 * lane]);
    auto stageV = [&](int buf, int it) {
        const float* vq = vp + (long)(it * 8) * KVSTRIDE;
        uint32_t d = buf ? vs1 : vs0;
        #pragma unroll
        for (int t = 0; t < 8; t++)
            cp16(d + (uint32_t)(t * HDq) * 4, vq + (long)t * KVSTRIDE);
    };

    float4 out[4];
    #pragma unroll
    for (int h = 0; h < 4; h++) out[h] = make_float4(0.f, 0.f, 0.f, 0.f);
    float m_run = -1e30f, l_run = 0.f;   // state for head h = lane&3

    if (n_it > 0) { stageV(0, 0); cp_commit(); }

    for (int it = 0; it < n_it; it++) {
        const float* kq = kp + (long)(it * 8) * KVSTRIDE;

        // K group: batched LDG.128 (independent -> high MLP)
        float4 k4[8];
        #pragma unroll
        for (int t = 0; t < 8; t++) k4[t] = __ldcs((const float4*)(kq + t * KVSTRIDE));

        // prefetch next V group (always commit so wait_group 1 tracking is uniform)
        if (it + 1 < n_it) stageV((it + 1) & 1, it + 1);
        cp_commit();

        // ---- dot with fused stage-16 exchange: pairs (t, t+4); r[] halved ----
        float r[16];
        #pragma unroll
        for (int t = 0; t < 4; t++) {
            #pragma unroll
            for (int h = 0; h < 4; h++) {
                float a = k4[t].x * q[h].x;
                a = fmaf(k4[t].y, q[h].y, a);
                a = fmaf(k4[t].z, q[h].z, a);
                a = fmaf(k4[t].w, q[h].w, a);
                float bb = k4[t + 4].x * q[h].x;
                bb = fmaf(k4[t + 4].y, q[h].y, bb);
                bb = fmaf(k4[t + 4].z, q[h].z, bb);
                bb = fmaf(k4[t + 4].w, q[h].w, bb);
                bool  hi   = (lane & 16) != 0;
                float send = hi ? a : bb;
                float recv = __shfl_xor_sync(0xffffffffu, send, 16);
                r[t * 4 + h] = (hi ? bb : a) + recv;
            }
        }
        BFLY_STAGE(8) BFLY_STAGE(4) BFLY_STAGE(2) BFLY_STAGE(1)
        float s = r[0];                      // score for (t = lane>>2, h = lane&3)

        const int tok = warpStart + it * 8 + (lane >> 2);
        if (tok >= L) s = -1e30f;

        // per-head max / sum over 8 tokens (lanes stride 4 share a head)
        float mt = s;
        mt = fmaxf(mt, __shfl_xor_sync(0xffffffffu, mt, 4));
        mt = fmaxf(mt, __shfl_xor_sync(0xffffffffu, mt, 8));
        mt = fmaxf(mt, __shfl_xor_sync(0xffffffffu, mt, 16));
        float m_new = fmaxf(m_run, mt);
        float p  = __expf(s - m_new);
        float ps = p;
        ps += __shfl_xor_sync(0xffffffffu, ps, 4);
        ps += __shfl_xor_sync(0xffffffffu, ps, 8);
        ps += __shfl_xor_sync(0xffffffffu, ps, 16);
        float csc = __expf(m_run - m_new);
        l_run = l_run * csc + ps;
        m_run = m_new;

        // rescale accumulators (csc for head h lives in lane h)
        #pragma unroll
        for (int h = 0; h < 4; h++) {
            float c = __shfl_sync(0xffffffffu, csc, h);
            out[h].x *= c; out[h].y *= c; out[h].z *= c; out[h].w *= c;
        }

        // ---- V group resident; P·V ----
        cp_wait1();
        const float* V = &smbuf[w][it & 1][4 * lane];
        #pragma unroll
        for (int t = 0; t < 8; t++) {
            float4 v4 = *(const float4*)(V + t * HDq);
            #pragma unroll
            for (int h = 0; h < 4; h++) {
                float pp = __shfl_sync(0xffffffffu, p, t * 4 + h);
                out[h].x = fmaf(pp, v4.x, out[h].x);
                out[h].y = fmaf(pp, v4.y, out[h].y);
                out[h].z = fmaf(pp, v4.z, out[h].z);
                out[h].w = fmaf(pp, v4.w, out[h].w);
            }
        }
    }

    // ---- CTA-internal combine: overlay warp buffers on this warp's V smem ----
    float* wacc = &smbuf[w][0][0];            // [4][128]
    float* wml  = &smbuf[w][1][0];            // m[4], l at +8
    #pragma unroll
    for (int h = 0; h < 4; h++)
        *(float4*)&wacc[h * HDq + 4 * lane] = out[h];
    if (lane < 4) { wml[lane] = m_run; wml[8 + lane] = l_run; }
    __syncthreads();

    const int  gidx = b * KVHq + kvh;
    const long base = (long)gidx * NSPLIT * Gq + (long)split * Gq;
    #pragma unroll
    for (int h = 0; h < 4; h++) {
        float m0 = smbuf[0][1][h], m1 = smbuf[1][1][h];
        float m2 = smbuf[2][1][h], m3 = smbuf[3][1][h];
        float M = fmaxf(fmaxf(m0, m1), fmaxf(m2, m3));
        float e0 = __expf(m0 - M), e1 = __expf(m1 - M);
        float e2 = __expf(m2 - M), e3 = __expf(m3 - M);
        float acc = e0 * smbuf[0][0][h * HDq + tid] + e1 * smbuf[1][0][h * HDq + tid]
                  + e2 * smbuf[2][0][h * HDq + tid] + e3 * smbuf[3][0][h * HDq + tid];
        P_acc[(base + h) * HDq + tid] = acc;
        if (tid == 0) {
            P_m[base + h] = M;
            P_l[base + h] = e0 * smbuf[0][1][8 + h] + e1 * smbuf[1][1][8 + h]
                          + e2 * smbuf[2][1][8 + h] + e3 * smbuf[3][1][8 + h];
        }
    }

    // ---- last-CTA-done global combine for this (b,kvh) ----
    __threadfence();
    if (tid == 0) {
        int old = atomicAdd(&P_cnt[gidx], 1);
        s_last = (old == ns - 1);
    }
    __syncthreads();
    if (!s_last) return;
    if (tid == 0) P_cnt[gidx] = 0;          // reset for next graph replay

    const long base0 = (long)gidx * NSPLIT * Gq;
    #pragma unroll
    for (int h = 0; h < 4; h++) {
        float ms[NSPLIT], ls[NSPLIT];
        #pragma unroll
        for (int s = 0; s < NSPLIT; s++) {
            bool v = s < ns;
            ms[s] = v ? ldcg(&P_m[base0 + s * Gq + h]) : -1e30f;
            ls[s] = v ? ldcg(&P_l[base0 + s * Gq + h]) : 0.f;
        }
        float M = -1e30f;
        #pragma unroll
        for (int s = 0; s < NSPLIT; s++) M = fmaxf(M, ms[s]);
        float acc = 0.f, l = 0.f;
        #pragma unroll
        for (int s = 0; s < NSPLIT; s++) {
            float e = __expf(ms[s] - M);
            l += e * ls[s];
            float a = (s < ns) ? ldcg(&P_acc[(base0 + s * Gq + h) * HDq + tid]) : 0.f;
            acc += e * a;
        }
        outp[((long)b * Hq + kvh * Gq + h) * HDq + tid] = acc / l;
    }
}

extern "C" void kernel_launch(void* const* d_in, const int* in_sizes, int n_in,
                              void* d_out, int out_size)
{
    const int*   req_to_token = (const int*)d_in[0];
    const int*   req_pool     = (const int*)d_in[1];
    const int*   seq_lens     = (const int*)d_in[2];
    const float* query        = (const float*)d_in[3];
    const float* k_cache      = (const float*)d_in[4];
    const float* v_cache      = (const float*)d_in[5];
    float*       out          = (float*)d_out;

    dim3 grid1(NSPLIT, KVHq, Bq);
    attn_split_kernel<<<grid1, BDIM>>>(
        req_to_token, req_pool, seq_lens, query, k_cache, v_cache, out);
}

// round 10
// speedup vs baseline: 1.3792x; 1.1454x over previous
#include <cuda_runtime.h>
#include <cstdint>

// Problem constants
#define Bq      64
#define SMAX    2048
#define PAGEq   128
#define Hq      32
#define KVHq    8
#define Gq      4
#define HDq     128
#define SCALEq  0.08838834764831845f   // 128^-0.5

#define CHUNK   256        // tokens per CTA split
#define NSPLIT  8          // SMAX / CHUNK
#define WTOK    64         // tokens per warp
#define BDIM    128

#define KVSTRIDE  (KVHq*HDq)                 // floats between tokens
#define BLKSTRIDE ((long)PAGEq*KVHq*HDq)     // floats per KV block

// split partials + completion counters
__device__ float P_acc[Bq*KVHq*NSPLIT*Gq*HDq];
__device__ float P_m[Bq*KVHq*NSPLIT*Gq];
__device__ float P_l[Bq*KVHq*NSPLIT*Gq];
__device__ int   P_cnt[Bq*KVHq];             // zero-init; reset by combiner each launch

__device__ __forceinline__ float ldcg(const float* p) {
    float v; asm volatile("ld.global.cg.f32 %0, [%1];" : "=f"(v) : "l"(p)); return v;
}
__device__ __forceinline__ void cp16(uint32_t s, const void* g) {
    asm volatile("cp.async.cg.shared.global [%0], [%1], 16;\n" :: "r"(s), "l"(g));
}
__device__ __forceinline__ void cp_commit() { asm volatile("cp.async.commit_group;\n"); }
__device__ __forceinline__ void cp_wait1()  { asm volatile("cp.async.wait_group 1;\n"); }
__device__ __forceinline__ void pfL2(const void* g) {
    asm volatile("prefetch.global.L2 [%0];" :: "l"(g));
}

// one butterfly stage of the 32-value cross-lane reduction
#define BFLY_STAGE(D)                                              \
    _Pragma("unroll")                                              \
    for (int j = 0; j < (D); j++) {                                \
        bool  hi   = (lane & (D)) != 0;                            \
        float send = hi ? r[j] : r[j + (D)];                       \
        float recv = __shfl_xor_sync(0xffffffffu, send, (D));      \
        float keep = hi ? r[j + (D)] : r[j];                       \
        r[j] = keep + recv;                                        \
    }

__global__ __launch_bounds__(BDIM, 5) void attn_split_kernel(
    const int* __restrict__ req_to_token,
    const int* __restrict__ req_pool,
    const int* __restrict__ seq_lens,
    const float* __restrict__ query,
    const float* __restrict__ k_cache,
    const float* __restrict__ v_cache,
    float* __restrict__ outp)
{
    // per-warp V staging (double buffer); overlaid by warp-combine buffers after the loop
    __shared__ float smbuf[4][2][8 * HDq];   // 32 KB
    __shared__ int   s_last;

    const int split = blockIdx.x;
    const int kvh   = blockIdx.y;
    const int b     = blockIdx.z;

    const int L  = seq_lens[b];
    const int c0 = split * CHUNK;
    if (c0 >= L) return;
    const int ns = (L + CHUNK - 1) / CHUNK;

    const int w    = threadIdx.x >> 5;
    const int lane = threadIdx.x & 31;
    const int tid  = threadIdx.x;

    // ---- Q in registers, pre-scaled. lane owns d = 4*lane..4*lane+3 ----
    float4 q[4];
    {
        const float* Qb = query + ((long)b * Hq + kvh * Gq) * HDq + 4 * lane;
        #pragma unroll
        for (int h = 0; h < 4; h++) {
            float4 t = *(const float4*)(Qb + h * HDq);
            q[h] = make_float4(t.x * SCALEq, t.y * SCALEq, t.z * SCALEq, t.w * SCALEq);
        }
    }

    // ---- warp token range (stays within one KV page) ----
    const int warpStart = c0 + w * WTOK;
    const int req  = req_pool[b];
    const long blk = (long)(req_to_token[req * SMAX + (warpStart >> 7) * PAGEq] >> 7);
    const long off = blk * BLKSTRIDE + (long)(warpStart & 127) * KVSTRIDE + kvh * HDq + 4 * lane;
    const float* kp = k_cache + off;
    const float* vp = v_cache + off;

    // warp-wide K prefetch base: lane (t*4+line) covers token t, 128B line 'line'
    // of the group: one prefetch instruction warms the whole next 4KB K group.
    const float* kPF = kp - 4 * lane + (long)(lane >> 2) * KVSTRIDE + (lane & 3) * 32;

    int nt = L - warpStart;
    if (nt < 0) nt = 0;
    if (nt > WTOK) nt = WTOK;
    const int n_it = (nt + 7) >> 3;

    // this lane's V smem slices
    const uint32_t vs0 = (uint32_t)__cvta_generic_to_shared(&smbuf[w][0][4 * lane]);
    const uint32_t vs1 = (uint32_t)__cvta_generic_to_shared(&smbuf[w][1][4 * lane]);
    auto stageV = [&](int buf, int it) {
        const float* vq = vp + (long)(it * 8) * KVSTRIDE;
        uint32_t d = buf ? vs1 : vs0;
        #pragma unroll
        for (int t = 0; t < 8; t++)
            cp16(d + (uint32_t)(t * HDq) * 4, vq + (long)t * KVSTRIDE);
    };

    float4 out[4];
    #pragma unroll
    for (int h = 0; h < 4; h++) out[h] = make_float4(0.f, 0.f, 0.f, 0.f);
    float m_run = -1e30f, l_run = 0.f;   // state for head h = lane&3

    if (n_it > 0) { stageV(0, 0); cp_commit(); }

    for (int it = 0; it < n_it; it++) {
        // K group in registers (batched -> high MLP)
        const float* kq = kp + (long)(it * 8) * KVSTRIDE;
        float4 k4[8];
        #pragma unroll
        for (int t = 0; t < 8; t++) k4[t] = __ldcs((const float4*)(kq + t * KVSTRIDE));

        // warm next K group in L2 (one warp-wide instruction, 32 lines = 4KB)
        if (it + 1 < n_it) pfL2(kPF + (long)((it + 1) * 8) * KVSTRIDE);

        // prefetch next V group (always commit so wait_group 1 tracks correctly)
        if (it + 1 < n_it) stageV((it + 1) & 1, it + 1);
        cp_commit();

        // per-lane partial dot for (token t, head h)
        float r[32];
        #pragma unroll
        for (int t = 0; t < 8; t++) {
            #pragma unroll
            for (int h = 0; h < 4; h++) {
                float a = k4[t].x * q[h].x;
                a = fmaf(k4[t].y, q[h].y, a);
                a = fmaf(k4[t].z, q[h].z, a);
                a = fmaf(k4[t].w, q[h].w, a);
                r[t * 4 + h] = a;
            }
        }

        // 32-value butterfly: lane l ends with score for (t = l>>2, h = l&3)
        BFLY_STAGE(16) BFLY_STAGE(8) BFLY_STAGE(4) BFLY_STAGE(2) BFLY_STAGE(1)
        float s = r[0];

        const int tok = warpStart + it * 8 + (lane >> 2);
        if (tok >= L) s = -1e30f;

        // per-head max / sum over the 8 tokens (lanes stride 4 share a head)
        float mt = s;
        mt = fmaxf(mt, __shfl_xor_sync(0xffffffffu, mt, 4));
        mt = fmaxf(mt, __shfl_xor_sync(0xffffffffu, mt, 8));
        mt = fmaxf(mt, __shfl_xor_sync(0xffffffffu, mt, 16));
        float m_new = fmaxf(m_run, mt);
        float p  = __expf(s - m_new);
        float ps = p;
        ps += __shfl_xor_sync(0xffffffffu, ps, 4);
        ps += __shfl_xor_sync(0xffffffffu, ps, 8);
        ps += __shfl_xor_sync(0xffffffffu, ps, 16);
        float csc = __expf(m_run - m_new);
        l_run = l_run * csc + ps;
        m_run = m_new;

        // rescale accumulators (csc for head h lives in lane h)
        #pragma unroll
        for (int h = 0; h < 4; h++) {
            float c = __shfl_sync(0xffffffffu, csc, h);
            out[h].x *= c; out[h].y *= c; out[h].z *= c; out[h].w *= c;
        }

        // V group is ready (previous group's cp.async drained; lane-local data)
        cp_wait1();
        const float* V = &smbuf[w][it & 1][4 * lane];
        #pragma unroll
        for (int t = 0; t < 8; t++) {
            float4 v4 = *(const float4*)(V + t * HDq);
            #pragma unroll
            for (int h = 0; h < 4; h++) {
                float pp = __shfl_sync(0xffffffffu, p, t * 4 + h);
                out[h].x = fmaf(pp, v4.x, out[h].x);
                out[h].y = fmaf(pp, v4.y, out[h].y);
                out[h].z = fmaf(pp, v4.z, out[h].z);
                out[h].w = fmaf(pp, v4.w, out[h].w);
            }
        }
    }

    // ---- CTA-internal combine: overlay warp buffers on this warp's V smem ----
    float* wacc = &smbuf[w][0][0];            // [4][128]
    float* wml  = &smbuf[w][1][0];            // m[4], l at +8
    #pragma unroll
    for (int h = 0; h < 4; h++)
        *(float4*)&wacc[h * HDq + 4 * lane] = out[h];
    if (lane < 4) { wml[lane] = m_run; wml[8 + lane] = l_run; }
    __syncthreads();

    const int  gidx = b * KVHq + kvh;
    const long base = (long)gidx * NSPLIT * Gq + (long)split * Gq;
    #pragma unroll
    for (int h = 0; h < 4; h++) {
        float m0 = smbuf[0][1][h], m1 = smbuf[1][1][h];
        float m2 = smbuf[2][1][h], m3 = smbuf[3][1][h];
        float M = fmaxf(fmaxf(m0, m1), fmaxf(m2, m3));
        float e0 = __expf(m0 - M), e1 = __expf(m1 - M);
        float e2 = __expf(m2 - M), e3 = __expf(m3 - M);
        float acc = e0 * smbuf[0][0][h * HDq + tid] + e1 * smbuf[1][0][h * HDq + tid]
                  + e2 * smbuf[2][0][h * HDq + tid] + e3 * smbuf[3][0][h * HDq + tid];
        P_acc[(base + h) * HDq + tid] = acc;
        if (tid == 0) {
            P_m[base + h] = M;
            P_l[base + h] = e0 * smbuf[0][1][8 + h] + e1 * smbuf[1][1][8 + h]
                          + e2 * smbuf[2][1][8 + h] + e3 * smbuf[3][1][8 + h];
        }
    }

    // ---- last-CTA-done global combine for this (b,kvh) ----
    __threadfence();
    if (tid == 0) {
        int old = atomicAdd(&P_cnt[gidx], 1);
        s_last = (old == ns - 1);
    }
    __syncthreads();
    if (!s_last) return;
    if (tid == 0) P_cnt[gidx] = 0;          // reset for next graph replay

    const long base0 = (long)gidx * NSPLIT * Gq;
    #pragma unroll
    for (int h = 0; h < 4; h++) {
        float ms[NSPLIT], ls[NSPLIT];
        #pragma unroll
        for (int s = 0; s < NSPLIT; s++) {
            bool v = s < ns;
            ms[s] = v ? ldcg(&P_m[base0 + s * Gq + h]) : -1e30f;
            ls[s] = v ? ldcg(&P_l[base0 + s * Gq + h]) : 0.f;
        }
        float M = -1e30f;
        #pragma unroll
        for (int s = 0; s < NSPLIT; s++) M = fmaxf(M, ms[s]);
        float acc = 0.f, l = 0.f;
        #pragma unroll
        for (int s = 0; s < NSPLIT; s++) {
            float e = __expf(ms[s] - M);
            l += e * ls[s];
            float a = (s < ns) ? ldcg(&P_acc[(base0 + s * Gq + h) * HDq + tid]) : 0.f;
            acc += e * a;
        }
        outp[((long)b * Hq + kvh * Gq + h) * HDq + tid] = acc / l;
    }
}

extern "C" void kernel_launch(void* const* d_in, const int* in_sizes, int n_in,
                              void* d_out, int out_size)
{
    const int*   req_to_token = (const int*)d_in[0];
    const int*   req_pool     = (const int*)d_in[1];
    const int*   seq_lens     = (const int*)d_in[2];
    const float* query        = (const float*)d_in[3];
    const float* k_cache      = (const float*)d_in[4];
    const float* v_cache      = (const float*)d_in[5];
    float*       out          = (float*)d_out;

    dim3 grid1(NSPLIT, KVHq, Bq);
    attn_split_kernel<<<grid1, BDIM>>>(
        req_to_token, req_pool, seq_lens, query, k_cache, v_cache, out);
}